// round 16
// baseline (speedup 1.0000x reference)
#include <cuda_runtime.h>
#include <math.h>
#include <stdint.h>

// Problem constants
#define N_B     32
#define C_DIM   384
#define HW      3136        // 56*56
#define M_DIM   8
#define D_MODEL 768
#define E_DIM   768         // 2*C
#define KV_N    (M_DIM * E_DIM)   // 6144 per batch

// ---------------- device scratch -----------------------------------------------
#define NSPLIT 4
#define SPLIT_F4 (N_B * KV_N / 4)                       // 49152 float4 per split
__device__ __align__(16) float g_kvp[NSPLIT * N_B * KV_N]; // raw GEMM partials

// ================= Kernel 1: split-K GEMM partials, reg-prefetch pipelined =====
#define BM 32
#define BN 64
#define BK 32
#define DSPL (D_MODEL / NSPLIT)   // 192 -> 6 K-iters
#define NIT  (DSPL / BK)          // 6

__global__ __launch_bounds__(256) void kvp_kernel(
    const float* __restrict__ gf,
    const float* __restrict__ W)
{
    __shared__ float As[BK][BM + 2];
    __shared__ float Bs[BK][BN + 4];

    const int tid = threadIdx.x;
    const int tx  = tid & 15;
    const int ty  = tid >> 4;
    const int eb  = blockIdx.x * BN;
    const int rb  = blockIdx.y * BM;
    const int s   = blockIdx.z;
    const int kb0 = s * DSPL;

    float acc[2][4];
    #pragma unroll
    for (int i = 0; i < 2; i++)
        #pragma unroll
        for (int j = 0; j < 4; j++) acc[i][j] = 0.f;

    // register prefetch buffers
    float ar[4], br[8], arn[4], brn[8];

    // prologue: load tile 0 into regs
    #pragma unroll
    for (int i = 0; i < 4; i++) {
        int idx = tid + i * 256;
        ar[i] = gf[(size_t)(rb + (idx >> 5)) * D_MODEL + kb0 + (idx & 31)];
    }
    #pragma unroll
    for (int i = 0; i < 8; i++) {
        int idx = tid + i * 256;
        br[i] = W[(size_t)(eb + (idx >> 5)) * D_MODEL + kb0 + (idx & 31)];
    }

    for (int it = 0; it < NIT; it++) {
        // store current tile to smem
        #pragma unroll
        for (int i = 0; i < 4; i++) {
            int idx = tid + i * 256;
            As[idx & 31][idx >> 5] = ar[i];
        }
        #pragma unroll
        for (int i = 0; i < 8; i++) {
            int idx = tid + i * 256;
            Bs[idx & 31][idx >> 5] = br[i];
        }
        __syncthreads();

        // prefetch next tile into registers (overlaps the FMA block below)
        if (it + 1 < NIT) {
            int kb = kb0 + (it + 1) * BK;
            #pragma unroll
            for (int i = 0; i < 4; i++) {
                int idx = tid + i * 256;
                arn[i] = gf[(size_t)(rb + (idx >> 5)) * D_MODEL + kb + (idx & 31)];
            }
            #pragma unroll
            for (int i = 0; i < 8; i++) {
                int idx = tid + i * 256;
                brn[i] = W[(size_t)(eb + (idx >> 5)) * D_MODEL + kb + (idx & 31)];
            }
        }

        #pragma unroll
        for (int kk = 0; kk < BK; kk++) {
            float2 av = *(const float2*)&As[kk][ty * 2];
            float4 bv = *(const float4*)&Bs[kk][tx * 4];
            acc[0][0] += av.x * bv.x; acc[0][1] += av.x * bv.y;
            acc[0][2] += av.x * bv.z; acc[0][3] += av.x * bv.w;
            acc[1][0] += av.y * bv.x; acc[1][1] += av.y * bv.y;
            acc[1][2] += av.y * bv.z; acc[1][3] += av.y * bv.w;
        }
        __syncthreads();

        #pragma unroll
        for (int i = 0; i < 4; i++) ar[i] = arn[i];
        #pragma unroll
        for (int i = 0; i < 8; i++) br[i] = brn[i];
    }

    float* dst = g_kvp + (size_t)s * (N_B * KV_N);
    #pragma unroll
    for (int r = 0; r < 2; r++) {
        float4 o = make_float4(acc[r][0], acc[r][1], acc[r][2], acc[r][3]);
        *(float4*)&dst[(size_t)(rb + ty * 2 + r) * E_DIM + eb + tx * 4] = o;
    }
}

// ================= Kernel 2: register-resident attention ========================
// CTA = 256 threads = 8 warps x 32 pixels. Warp q owns channels [48q, 48q+48).
// x lives in 48 registers per thread: gmem -> regs -> gmem, NO x smem traffic.
// K/V staged in smem from the 4 split-K partials (+bias+clip folded in, L2-hot).
#define TILE_P 32
#define NTH2   256

// smem (floats): Ks 3072 | Vs 3072 | part 2048 | attnw 256
#define OFF_VS2  3072
#define OFF_PART 6144
#define OFF_AT2  8192
#define SM2_FLOATS 8448          // 33792 B

__global__ __launch_bounds__(NTH2, 3) void attn_reg(
    const float* __restrict__ x,
    const float* __restrict__ bias,
    float* __restrict__ out)
{
    __shared__ float smem2[SM2_FLOATS];
    float* Ks    = smem2;               // [k][c] rows of 384
    float* Vs    = smem2 + OFF_VS2;     // [k][c]
    float* part  = smem2 + OFF_PART;    // [q][k][p] : q*256 + k*32 + p
    float* attnw = smem2 + OFF_AT2;     // [k][p]    : k*32 + p

    const int tid = threadIdx.x;
    const int n   = blockIdx.y;
    const int p0  = blockIdx.x * TILE_P;
    const int q   = tid >> 5;           // warp id 0..7
    const int p   = tid & 31;           // lane = pixel

    // ---- load my 48 x values into registers (coalesced 128B warp loads) ----
    float xr[48];
    {
        const float* xb = x + ((size_t)n * C_DIM + q * 48) * HW + p0 + p;
        #pragma unroll
        for (int i = 0; i < 48; i++) xr[i] = __ldg(xb + (size_t)i * HW);
    }

    // ---- stage K,V: combine 4 split partials + bias + clip (L2-hot) ----
    {
        const float4* pp = (const float4*)g_kvp;
        const float4* b4 = (const float4*)bias;
        const int base = n * (KV_N / 4);
        #pragma unroll
        for (int t = 0; t < 6; t++) {
            int i = tid + t * NTH2;
            float4 a  = pp[0 * SPLIT_F4 + base + i];
            float4 v1 = pp[1 * SPLIT_F4 + base + i];
            float4 v2 = pp[2 * SPLIT_F4 + base + i];
            float4 v3 = pp[3 * SPLIT_F4 + base + i];
            a.x += v1.x + v2.x + v3.x;
            a.y += v1.y + v2.y + v3.y;
            a.z += v1.z + v2.z + v3.z;
            a.w += v1.w + v2.w + v3.w;
            int m = i / 192;            // k row
            int j = i - m * 192;        // float4 within row
            float4 bb = b4[j];
            float4 o;
            o.x = fminf(fmaxf(a.x + bb.x, 0.f), 6.f);
            o.y = fminf(fmaxf(a.y + bb.y, 0.f), 6.f);
            o.z = fminf(fmaxf(a.z + bb.z, 0.f), 6.f);
            o.w = fminf(fmaxf(a.w + bb.w, 0.f), 6.f);
            int e = j * 4;
            if (e < C_DIM) *(float4*)&Ks[m * C_DIM + e] = o;
            else           *(float4*)&Vs[m * C_DIM + (e - C_DIM)] = o;
        }
    }
    __syncthreads();

    // ---- phase 1: partial scores over my 48 channels ----
    {
        float acc[8];
        #pragma unroll
        for (int k = 0; k < 8; k++) acc[k] = 0.f;

        const float* Kq = Ks + q * 48;
        #pragma unroll
        for (int i4 = 0; i4 < 12; i4++) {
            #pragma unroll
            for (int k = 0; k < 8; k++) {
                float4 kk = *(const float4*)(Kq + k * C_DIM + i4 * 4);  // broadcast
                acc[k] += xr[i4*4+0] * kk.x + xr[i4*4+1] * kk.y
                        + xr[i4*4+2] * kk.z + xr[i4*4+3] * kk.w;
            }
        }
        // transposed partial store: conflict-free scalar STS
        #pragma unroll
        for (int k = 0; k < 8; k++) part[q * 256 + k * 32 + p] = acc[k];
    }
    __syncthreads();

    // ---- reduce over q + softmax (warp 0) ----
    if (tid < 32) {
        float s[8];
        #pragma unroll
        for (int k = 0; k < 8; k++) {
            float v = 0.f;
            #pragma unroll
            for (int qq = 0; qq < 8; qq++) v += part[qq * 256 + k * 32 + tid];
            s[k] = v;
        }
        float mx = s[0];
        #pragma unroll
        for (int k = 1; k < 8; k++) mx = fmaxf(mx, s[k]);
        float sum = 0.f;
        #pragma unroll
        for (int k = 0; k < 8; k++) { s[k] = __expf(s[k] - mx); sum += s[k]; }
        float inv = 1.0f / sum;
        #pragma unroll
        for (int k = 0; k < 8; k++) attnw[k * 32 + tid] = s[k] * inv;
    }
    __syncthreads();

    // ---- phase 2: out = x + attn @ V (x from registers, coalesced stores) ----
    {
        float a[8];
        #pragma unroll
        for (int k = 0; k < 8; k++) a[k] = attnw[k * 32 + p];   // conflict-free

        const float* Vq = Vs + q * 48;
        float* op = out + ((size_t)n * C_DIM + q * 48) * HW + p0 + p;
        #pragma unroll
        for (int i4 = 0; i4 < 12; i4++) {
            float o0 = xr[i4*4+0], o1 = xr[i4*4+1], o2 = xr[i4*4+2], o3 = xr[i4*4+3];
            #pragma unroll
            for (int k = 0; k < 8; k++) {
                float4 vv = *(const float4*)(Vq + k * C_DIM + i4 * 4);  // broadcast
                o0 += a[k] * vv.x; o1 += a[k] * vv.y;
                o2 += a[k] * vv.z; o3 += a[k] * vv.w;
            }
            op[(size_t)(i4*4+0) * HW] = o0;
            op[(size_t)(i4*4+1) * HW] = o1;
            op[(size_t)(i4*4+2) * HW] = o2;
            op[(size_t)(i4*4+3) * HW] = o3;
        }
    }
}

// ================= launch ======================================================
extern "C" void kernel_launch(void* const* d_in, const int* in_sizes, int n_in,
                              void* d_out, int out_size)
{
    const float* x  = (const float*)d_in[0];
    const float* gf = (const float*)d_in[1];
    const float* W  = (const float*)d_in[2];
    const float* b  = (const float*)d_in[3];
    float* out = (float*)d_out;

    kvp_kernel<<<dim3(E_DIM / BN, (N_B * M_DIM) / BM, NSPLIT), 256>>>(gf, W);
    attn_reg<<<dim3(HW / TILE_P, N_B), NTH2>>>(x, b, out);
}